// round 12
// baseline (speedup 1.0000x reference)
#include <cuda_runtime.h>
#include <math.h>

#define BATCH 16
#define HH 512
#define WW 512
#define W4 (WW / 4)
#define WIN 15
#define RAD 7
#define NT 256
#define NB1 512          // k1: (4, 8, 16)
#define NB2 1024         // k2: (4, 16, 16)
#define NBTOT (NB1 + NB2)

__device__ float4 g_vI[(size_t)BATCH * HH * W4];
__device__ float4 g_vJ[(size_t)BATCH * HH * W4];
__device__ double g_part[NBTOT][6];
__device__ unsigned int g_count = 0;

// Volatile vectorized load: ptxas cannot reorder/sink these, so consecutive
// calls stay batched -> forced memory-level parallelism.
__device__ __forceinline__ float4 ldg128v(const float4* p) {
    float4 v;
    asm volatile("ld.global.nc.v4.f32 {%0,%1,%2,%3}, [%4];"
                 : "=f"(v.x), "=f"(v.y), "=f"(v.z), "=f"(v.w) : "l"(p));
    return v;
}

__device__ __forceinline__ void warp_red3(float& a, float& b, float& c) {
    #pragma unroll
    for (int off = 16; off > 0; off >>= 1) {
        a += __shfl_xor_sync(0xFFFFFFFFu, a, off);
        b += __shfl_xor_sync(0xFFFFFFFFu, b, off);
        c += __shfl_xor_sync(0xFFFFFFFFu, c, off);
    }
}

// ========================= Kernel 1: vertical pass ===========================
__global__ void __launch_bounds__(NT, 2)
ncc_k1(const float* __restrict__ I, const float* __restrict__ J) {
    const int tid  = threadIdx.x;
    const int lane = tid & 31;
    const int wrp  = tid >> 5;
    const int bx = blockIdx.x, by = blockIdx.y, bz = blockIdx.z;

    const int c4 = bx * 32 + lane;
    const int y0 = (by * 8 + wrp) * 8;
    const int cx = c4 * 4;

    const float4* __restrict__ I4 = (const float4*)I + (size_t)bz * HH * W4;
    const float4* __restrict__ J4 = (const float4*)J + (size_t)bz * HH * W4;
    float4* __restrict__ vI = g_vI + (size_t)bz * HH * W4;
    float4* __restrict__ vJ = g_vJ + (size_t)bz * HH * W4;

    const float wx0 = (float)(min(cx + 0 + RAD, WW - 1) - max(cx + 0 - RAD, 0) + 1);
    const float wx1 = (float)(min(cx + 1 + RAD, WW - 1) - max(cx + 1 - RAD, 0) + 1);
    const float wx2 = (float)(min(cx + 2 + RAD, WW - 1) - max(cx + 2 - RAD, 0) + 1);
    const float wx3 = (float)(min(cx + 3 + RAD, WW - 1) - max(cx + 3 - RAD, 0) + 1);

    float4 VI = make_float4(0.f, 0.f, 0.f, 0.f);
    float4 VJ = make_float4(0.f, 0.f, 0.f, 0.f);
    float pII = 0.f, pJJ = 0.f, pIJ = 0.f;
    const float4 zero = make_float4(0.f, 0.f, 0.f, 0.f);

    // Init window rows y0-7 .. y0+7, batched 5 row-pairs (10 loads) at a time.
    #pragma unroll
    for (int base = 0; base < WIN; base += 5) {
        float4 bi[5], bj[5];
        #pragma unroll
        for (int t = 0; t < 5; t++) {
            const int gy = y0 - RAD + base + t;
            bi[t] = zero; bj[t] = zero;
            if (gy >= 0 && gy < HH) {
                bi[t] = ldg128v(I4 + gy * W4 + c4);
                bj[t] = ldg128v(J4 + gy * W4 + c4);
            }
        }
        #pragma unroll
        for (int t = 0; t < 5; t++) {
            const int k  = base + t;
            const int gy = y0 - RAD + k;
            VI.x += bi[t].x; VI.y += bi[t].y; VI.z += bi[t].z; VI.w += bi[t].w;
            VJ.x += bj[t].x; VJ.y += bj[t].y; VJ.z += bj[t].z; VJ.w += bj[t].w;
            if (k >= RAD) {
                const float wy = (float)(min(gy + RAD, HH - 1) - max(gy - RAD, 0) + 1);
                pII += wy * (wx0 * bi[t].x * bi[t].x + wx1 * bi[t].y * bi[t].y +
                             wx2 * bi[t].z * bi[t].z + wx3 * bi[t].w * bi[t].w);
                pJJ += wy * (wx0 * bj[t].x * bj[t].x + wx1 * bj[t].y * bj[t].y +
                             wx2 * bj[t].z * bj[t].z + wx3 * bj[t].w * bj[t].w);
                pIJ += wy * (wx0 * bi[t].x * bj[t].x + wx1 * bi[t].y * bj[t].y +
                             wx2 * bi[t].z * bj[t].z + wx3 * bi[t].w * bj[t].w);
            }
        }
    }
    vI[(size_t)y0 * W4 + c4] = VI;
    vJ[(size_t)y0 * W4 + c4] = VJ;

    // Slides: output rows y0+1..y0+7, batched 2 slides (8 loads) at a time.
    #pragma unroll
    for (int j0 = 0; j0 < 7; j0 += 2) {
        const int nslides = (j0 + 2 <= 7) ? 2 : 1;
        float4 ni[2], nj[2], oi[2], oj[2];
        #pragma unroll
        for (int t = 0; t < 2; t++) {
            ni[t] = zero; nj[t] = zero; oi[t] = zero; oj[t] = zero;
            if (t < nslides) {
                const int gyn = y0 + RAD + 1 + j0 + t;
                const int gyo = y0 - RAD + j0 + t;
                if (gyn < HH) {
                    ni[t] = ldg128v(I4 + gyn * W4 + c4);
                    nj[t] = ldg128v(J4 + gyn * W4 + c4);
                }
                if (gyo >= 0) {
                    oi[t] = ldg128v(I4 + gyo * W4 + c4);
                    oj[t] = ldg128v(J4 + gyo * W4 + c4);
                }
            }
        }
        #pragma unroll
        for (int t = 0; t < 2; t++) {
            if (t < nslides) {
                VI.x += ni[t].x - oi[t].x; VI.y += ni[t].y - oi[t].y;
                VI.z += ni[t].z - oi[t].z; VI.w += ni[t].w - oi[t].w;
                VJ.x += nj[t].x - oj[t].x; VJ.y += nj[t].y - oj[t].y;
                VJ.z += nj[t].z - oj[t].z; VJ.w += nj[t].w - oj[t].w;
                vI[(size_t)(y0 + 1 + j0 + t) * W4 + c4] = VI;
                vJ[(size_t)(y0 + 1 + j0 + t) * W4 + c4] = VJ;
            }
        }
    }

    warp_red3(pII, pJJ, pIJ);
    __shared__ double red[NT / 32][3];
    if (lane == 0) {
        red[wrp][0] = (double)pII; red[wrp][1] = (double)pJJ; red[wrp][2] = (double)pIJ;
    }
    __syncthreads();
    if (tid == 0) {
        double t0 = 0, t1 = 0, t2 = 0;
        #pragma unroll
        for (int w = 0; w < NT / 32; w++) { t0 += red[w][0]; t1 += red[w][1]; t2 += red[w][2]; }
        const int bid = bx + 4 * (by + 8 * bz);
        g_part[bid][0] = t0; g_part[bid][1] = t1; g_part[bid][2] = t2;
        g_part[bid][3] = 0;  g_part[bid][4] = 0;  g_part[bid][5] = 0;
    }
}

// ==================== Kernel 2: horizontal pass + finalize ===================
// 4 rows/thread processed in 2 pairs; each pair = 20 volatile LDG.128 in flight.
__global__ void __launch_bounds__(NT, 2)
ncc_k2(float* __restrict__ out) {
    const int tid  = threadIdx.x;
    const int lane = tid & 31;
    const int wrp  = tid >> 5;
    const int bx = blockIdx.x, by = blockIdx.y, bz = blockIdx.z;

    const int c4 = bx * 32 + lane;
    float sII = 0.f, sJJ = 0.f, sIJ = 0.f;
    const float4 zero = make_float4(0.f, 0.f, 0.f, 0.f);

    #pragma unroll
    for (int pr = 0; pr < 2; pr++) {
        const int ya = by * 32 + wrp * 4 + pr * 2;
        const int yb = ya + 1;
        const float4* __restrict__ vIa = g_vI + ((size_t)bz * HH + ya) * W4;
        const float4* __restrict__ vJa = g_vJ + ((size_t)bz * HH + ya) * W4;
        const float4* __restrict__ vIb = g_vI + ((size_t)bz * HH + yb) * W4;
        const float4* __restrict__ vJb = g_vJ + ((size_t)bz * HH + yb) * W4;

        float4 ai[5], aj[5], bi[5], bj[5];
        #pragma unroll
        for (int c = 0; c < 5; c++) {
            const int i4 = c4 - 2 + c;
            const bool ok = (i4 >= 0) && (i4 < W4);
            ai[c] = ok ? ldg128v(vIa + i4) : zero;
            aj[c] = ok ? ldg128v(vJa + i4) : zero;
            bi[c] = ok ? ldg128v(vIb + i4) : zero;
            bj[c] = ok ? ldg128v(vJb + i4) : zero;
        }

        #pragma unroll
        for (int half = 0; half < 2; half++) {
            float rI[20], rJ[20];
            #pragma unroll
            for (int c = 0; c < 5; c++) {
                const float4 a = half ? bi[c] : ai[c];
                const float4 b = half ? bj[c] : aj[c];
                rI[4*c+0] = a.x; rI[4*c+1] = a.y; rI[4*c+2] = a.z; rI[4*c+3] = a.w;
                rJ[4*c+0] = b.x; rJ[4*c+1] = b.y; rJ[4*c+2] = b.z; rJ[4*c+3] = b.w;
            }
            float WI = 0.f, WJ = 0.f;
            #pragma unroll
            for (int i = 1; i <= WIN; i++) { WI += rI[i]; WJ += rJ[i]; }
            #pragma unroll
            for (int i = 0; i < 4; i++) {
                sII += WI * WI;
                sJJ += WJ * WJ;
                sIJ += WI * WJ;
                if (i < 3) {
                    WI += rI[i + 16] - rI[i + 1];
                    WJ += rJ[i + 16] - rJ[i + 1];
                }
            }
        }
    }

    warp_red3(sII, sJJ, sIJ);
    __shared__ double red[NT / 32][3];
    if (lane == 0) {
        red[wrp][0] = (double)sII; red[wrp][1] = (double)sJJ; red[wrp][2] = (double)sIJ;
    }
    __syncthreads();

    __shared__ int s_last;
    if (tid == 0) {
        double t3 = 0, t4 = 0, t5 = 0;
        #pragma unroll
        for (int w = 0; w < NT / 32; w++) { t3 += red[w][0]; t4 += red[w][1]; t5 += red[w][2]; }
        const int bid = NB1 + bx + 4 * (by + 16 * bz);
        g_part[bid][0] = 0;  g_part[bid][1] = 0;  g_part[bid][2] = 0;
        g_part[bid][3] = t3; g_part[bid][4] = t4; g_part[bid][5] = t5;
        __threadfence();
        unsigned int prev = atomicAdd(&g_count, 1u);
        s_last = (prev == NB2 - 1);
    }
    __syncthreads();

    if (s_last) {
        double c0 = 0, c1 = 0, c2 = 0, c3 = 0, c4d = 0, c5 = 0;
        for (int c = tid; c < NBTOT; c += NT) {
            c0 += g_part[c][0]; c1 += g_part[c][1]; c2 += g_part[c][2];
            c3 += g_part[c][3]; c4d += g_part[c][4]; c5 += g_part[c][5];
        }
        __shared__ double red2[NT / 32][6];
        #pragma unroll
        for (int off = 16; off > 0; off >>= 1) {
            c0 += __shfl_xor_sync(0xFFFFFFFFu, c0, off);
            c1 += __shfl_xor_sync(0xFFFFFFFFu, c1, off);
            c2 += __shfl_xor_sync(0xFFFFFFFFu, c2, off);
            c3 += __shfl_xor_sync(0xFFFFFFFFu, c3, off);
            c4d += __shfl_xor_sync(0xFFFFFFFFu, c4d, off);
            c5 += __shfl_xor_sync(0xFFFFFFFFu, c5, off);
        }
        if (lane == 0) {
            red2[wrp][0] = c0; red2[wrp][1] = c1; red2[wrp][2] = c2;
            red2[wrp][3] = c3; red2[wrp][4] = c4d; red2[wrp][5] = c5;
        }
        __syncthreads();
        if (tid == 0) {
            double t0 = 0, t1 = 0, t2 = 0, t3 = 0, t4 = 0, t5 = 0;
            #pragma unroll
            for (int w = 0; w < NT / 32; w++) {
                t0 += red2[w][0]; t1 += red2[w][1]; t2 += red2[w][2];
                t3 += red2[w][3]; t4 += red2[w][4]; t5 += red2[w][5];
            }
            const double inv = 1.0 / 225.0;
            const double cross = t2 - t5 * inv;
            const double iv    = t0 - t3 * inv;
            const double jv    = t1 - t4 * inv;
            out[0] = (float)(-(cross / sqrt(iv * jv)));
            g_count = 0;
        }
    }
}

extern "C" void kernel_launch(void* const* d_in, const int* in_sizes, int n_in,
                              void* d_out, int out_size) {
    const float* I = (const float*)d_in[0];
    const float* J = (const float*)d_in[1];
    float* out = (float*)d_out;

    dim3 g1(4, 8, 16);     // 512 CTAs
    ncc_k1<<<g1, NT>>>(I, J);
    dim3 g2(4, 16, 16);    // 1024 CTAs
    ncc_k2<<<g2, NT>>>(out);
}

// round 13
// speedup vs baseline: 1.4791x; 1.4791x over previous
#include <cuda_runtime.h>
#include <math.h>

#define BATCH 16
#define HH 512
#define WW 512
#define W4 (WW / 4)
#define WIN 15
#define RAD 7
#define SEG 28                 // output float4 columns per segment
#define GRX 5                  // ceil(128/28)
#define GRY 8                  // 512 rows / 64
#define NT 256
#define NBLOCKS (GRX * GRY * BATCH)   // 640

__device__ double g_part[NBLOCKS][6];
__device__ unsigned int g_count = 0;

__device__ __forceinline__ float4 shfl4(float4 v, int src) {
    float4 r;
    r.x = __shfl_sync(0xFFFFFFFFu, v.x, src);
    r.y = __shfl_sync(0xFFFFFFFFu, v.y, src);
    r.z = __shfl_sync(0xFFFFFFFFu, v.z, src);
    r.w = __shfl_sync(0xFFFFFFFFu, v.w, src);
    return r;
}

// Horizontal 15-tap window over the warp-held row of vertical sums.
// All lanes execute the shuffles; only 'own' lanes accumulate.
__device__ __forceinline__ void hstep(float4 VI, float4 VJ, bool own, int lane,
                                      float& sII, float& sJJ, float& sIJ) {
    const float4 m2I = shfl4(VI, lane - 2);
    const float4 m1I = shfl4(VI, lane - 1);
    const float4 p1I = shfl4(VI, lane + 1);
    const float4 p2I = shfl4(VI, lane + 2);
    const float4 m2J = shfl4(VJ, lane - 2);
    const float4 m1J = shfl4(VJ, lane - 1);
    const float4 p1J = shfl4(VJ, lane + 1);
    const float4 p2J = shfl4(VJ, lane + 2);

    float rI[20], rJ[20];
    rI[0]=m2I.x; rI[1]=m2I.y; rI[2]=m2I.z; rI[3]=m2I.w;
    rI[4]=m1I.x; rI[5]=m1I.y; rI[6]=m1I.z; rI[7]=m1I.w;
    rI[8]=VI.x;  rI[9]=VI.y;  rI[10]=VI.z; rI[11]=VI.w;
    rI[12]=p1I.x;rI[13]=p1I.y;rI[14]=p1I.z;rI[15]=p1I.w;
    rI[16]=p2I.x;rI[17]=p2I.y;rI[18]=p2I.z;rI[19]=p2I.w;
    rJ[0]=m2J.x; rJ[1]=m2J.y; rJ[2]=m2J.z; rJ[3]=m2J.w;
    rJ[4]=m1J.x; rJ[5]=m1J.y; rJ[6]=m1J.z; rJ[7]=m1J.w;
    rJ[8]=VJ.x;  rJ[9]=VJ.y;  rJ[10]=VJ.z; rJ[11]=VJ.w;
    rJ[12]=p1J.x;rJ[13]=p1J.y;rJ[14]=p1J.z;rJ[15]=p1J.w;
    rJ[16]=p2J.x;rJ[17]=p2J.y;rJ[18]=p2J.z;rJ[19]=p2J.w;

    float WI = 0.f, WJ = 0.f;
    #pragma unroll
    for (int i = 1; i <= WIN; i++) { WI += rI[i]; WJ += rJ[i]; }
    float a = 0.f, b = 0.f, c = 0.f;
    #pragma unroll
    for (int i = 0; i < 4; i++) {
        a += WI * WI;
        b += WJ * WJ;
        c += WI * WJ;
        if (i < 3) {
            WI += rI[i + 16] - rI[i + 1];
            WJ += rJ[i + 16] - rJ[i + 1];
        }
    }
    if (own) { sII += a; sJJ += b; sIJ += c; }
}

__global__ void __launch_bounds__(NT)
ncc_fused(const float* __restrict__ I, const float* __restrict__ J,
          float* __restrict__ out) {
    const int tid  = threadIdx.x;
    const int lane = tid & 31;
    const int wrp  = tid >> 5;
    const int bx = blockIdx.x, by = blockIdx.y, bz = blockIdx.z;

    // lane -> float4 column with 2-halo on each side of a 28-wide segment
    const int c4    = bx * SEG - 2 + lane;          // -2 .. 139
    const bool colok = (c4 >= 0) && (c4 < W4);
    const bool own   = (lane >= 2) && (lane < 2 + SEG) && (c4 < W4);  // c4>=0 implied
    const int cx = c4 * 4;

    float wx0 = 0.f, wx1 = 0.f, wx2 = 0.f, wx3 = 0.f;
    if (own) {
        wx0 = (float)(min(cx + 0 + RAD, WW - 1) - max(cx + 0 - RAD, 0) + 1);
        wx1 = (float)(min(cx + 1 + RAD, WW - 1) - max(cx + 1 - RAD, 0) + 1);
        wx2 = (float)(min(cx + 2 + RAD, WW - 1) - max(cx + 2 - RAD, 0) + 1);
        wx3 = (float)(min(cx + 3 + RAD, WW - 1) - max(cx + 3 - RAD, 0) + 1);
    }

    const float4* __restrict__ I4 = (const float4*)I + (size_t)bz * HH * W4;
    const float4* __restrict__ J4 = (const float4*)J + (size_t)bz * HH * W4;

    const int y0 = (by * 8 + wrp) * 8;              // warp's first output row
    const float4 zero = make_float4(0.f, 0.f, 0.f, 0.f);

    float4 VI = zero, VJ = zero;
    float pII = 0.f, pJJ = 0.f, pIJ = 0.f;
    float sII = 0.f, sJJ = 0.f, sIJ = 0.f;

    // ---- init vertical window rows y0-7 .. y0+7 (owned rows at k=7..14) ----
    #pragma unroll
    for (int k = 0; k < WIN; k++) {
        const int gy = y0 - RAD + k;                // <= 511 always
        float4 vi = zero, vj = zero;
        if (colok && gy >= 0) {
            vi = __ldg(I4 + gy * W4 + c4);
            vj = __ldg(J4 + gy * W4 + c4);
        }
        VI.x += vi.x; VI.y += vi.y; VI.z += vi.z; VI.w += vi.w;
        VJ.x += vj.x; VJ.y += vj.y; VJ.z += vj.z; VJ.w += vj.w;
        if (k >= RAD && own) {                      // owned pixel (gy, cx..cx+3)
            const float wy = (float)(min(gy + RAD, HH - 1) - max(gy - RAD, 0) + 1);
            pII += wy * (wx0 * vi.x * vi.x + wx1 * vi.y * vi.y +
                         wx2 * vi.z * vi.z + wx3 * vi.w * vi.w);
            pJJ += wy * (wx0 * vj.x * vj.x + wx1 * vj.y * vj.y +
                         wx2 * vj.z * vj.z + wx3 * vj.w * vj.w);
            pIJ += wy * (wx0 * vi.x * vj.x + wx1 * vi.y * vj.y +
                         wx2 * vi.z * vj.z + wx3 * vi.w * vj.w);
        }
    }
    hstep(VI, VJ, own, lane, sII, sJJ, sIJ);        // output row y0

    // ---- slides: output rows y0+1 .. y0+7 ----
    #pragma unroll
    for (int j = 0; j < 7; j++) {
        const int gyn = y0 + RAD + 1 + j;
        const int gyo = y0 - RAD + j;
        float4 ni = zero, nj = zero, oi = zero, oj = zero;
        if (colok && gyn < HH) {
            ni = __ldg(I4 + gyn * W4 + c4);
            nj = __ldg(J4 + gyn * W4 + c4);
        }
        if (colok && gyo >= 0) {
            oi = __ldg(I4 + gyo * W4 + c4);          // L1/L2 hit (recent)
            oj = __ldg(J4 + gyo * W4 + c4);
        }
        VI.x += ni.x - oi.x; VI.y += ni.y - oi.y;
        VI.z += ni.z - oi.z; VI.w += ni.w - oi.w;
        VJ.x += nj.x - oj.x; VJ.y += nj.y - oj.y;
        VJ.z += nj.z - oj.z; VJ.w += nj.w - oj.w;
        hstep(VI, VJ, own, lane, sII, sJJ, sIJ);    // output row y0+1+j
    }

    // ---- reductions: float within warp, double across warps/CTAs ----
    float r0 = pII, r1 = pJJ, r2 = pIJ, r3 = sII, r4 = sJJ, r5 = sIJ;
    #pragma unroll
    for (int off = 16; off > 0; off >>= 1) {
        r0 += __shfl_xor_sync(0xFFFFFFFFu, r0, off);
        r1 += __shfl_xor_sync(0xFFFFFFFFu, r1, off);
        r2 += __shfl_xor_sync(0xFFFFFFFFu, r2, off);
        r3 += __shfl_xor_sync(0xFFFFFFFFu, r3, off);
        r4 += __shfl_xor_sync(0xFFFFFFFFu, r4, off);
        r5 += __shfl_xor_sync(0xFFFFFFFFu, r5, off);
    }
    __shared__ double red[NT / 32][6];
    if (lane == 0) {
        red[wrp][0] = (double)r0; red[wrp][1] = (double)r1; red[wrp][2] = (double)r2;
        red[wrp][3] = (double)r3; red[wrp][4] = (double)r4; red[wrp][5] = (double)r5;
    }
    __syncthreads();

    __shared__ int s_last;
    const int bid = bx + GRX * (by + GRY * bz);
    if (tid == 0) {
        double t0 = 0, t1 = 0, t2 = 0, t3 = 0, t4 = 0, t5 = 0;
        #pragma unroll
        for (int w = 0; w < NT / 32; w++) {
            t0 += red[w][0]; t1 += red[w][1]; t2 += red[w][2];
            t3 += red[w][3]; t4 += red[w][4]; t5 += red[w][5];
        }
        g_part[bid][0] = t0; g_part[bid][1] = t1; g_part[bid][2] = t2;
        g_part[bid][3] = t3; g_part[bid][4] = t4; g_part[bid][5] = t5;
        __threadfence();
        unsigned int prev = atomicAdd(&g_count, 1u);
        s_last = (prev == NBLOCKS - 1);
    }
    __syncthreads();

    // ---- last CTA: global reduce + finalize ----
    if (s_last) {
        double c0 = 0, c1 = 0, c2 = 0, c3 = 0, c4d = 0, c5 = 0;
        for (int c = tid; c < NBLOCKS; c += NT) {
            c0 += g_part[c][0]; c1 += g_part[c][1]; c2 += g_part[c][2];
            c3 += g_part[c][3]; c4d += g_part[c][4]; c5 += g_part[c][5];
        }
        __shared__ double red2[NT / 32][6];
        #pragma unroll
        for (int off = 16; off > 0; off >>= 1) {
            c0 += __shfl_xor_sync(0xFFFFFFFFu, c0, off);
            c1 += __shfl_xor_sync(0xFFFFFFFFu, c1, off);
            c2 += __shfl_xor_sync(0xFFFFFFFFu, c2, off);
            c3 += __shfl_xor_sync(0xFFFFFFFFu, c3, off);
            c4d += __shfl_xor_sync(0xFFFFFFFFu, c4d, off);
            c5 += __shfl_xor_sync(0xFFFFFFFFu, c5, off);
        }
        if (lane == 0) {
            red2[wrp][0] = c0; red2[wrp][1] = c1; red2[wrp][2] = c2;
            red2[wrp][3] = c3; red2[wrp][4] = c4d; red2[wrp][5] = c5;
        }
        __syncthreads();
        if (tid == 0) {
            double t0 = 0, t1 = 0, t2 = 0, t3 = 0, t4 = 0, t5 = 0;
            #pragma unroll
            for (int w = 0; w < NT / 32; w++) {
                t0 += red2[w][0]; t1 += red2[w][1]; t2 += red2[w][2];
                t3 += red2[w][3]; t4 += red2[w][4]; t5 += red2[w][5];
            }
            const double inv = 1.0 / 225.0;
            const double cross = t2 - t5 * inv;
            const double iv    = t0 - t3 * inv;
            const double jv    = t1 - t4 * inv;
            out[0] = (float)(-(cross / sqrt(iv * jv)));
            g_count = 0;   // reset for next graph replay
        }
    }
}

extern "C" void kernel_launch(void* const* d_in, const int* in_sizes, int n_in,
                              void* d_out, int out_size) {
    const float* I = (const float*)d_in[0];
    const float* J = (const float*)d_in[1];
    float* out = (float*)d_out;

    dim3 grid(GRX, GRY, BATCH);   // (5, 8, 16) = 640 CTAs
    ncc_fused<<<grid, NT>>>(I, J, out);
}

// round 14
// speedup vs baseline: 1.5436x; 1.0436x over previous
#include <cuda_runtime.h>
#include <math.h>

#define BATCH 16
#define HH 512
#define WW 512
#define W4 (WW / 4)
#define WIN 15
#define RAD 7
#define SEG 28                 // output float4 columns per segment
#define GRX 5                  // ceil(128/28)
#define GRY 8                  // 512 rows / 64
#define NT 256
#define NBLOCKS (GRX * GRY * BATCH)   // 640

__device__ double g_part[NBLOCKS][6];
__device__ unsigned int g_count = 0;

// Horizontal 15-tap window sums for this lane's 4 output columns via
// prefix/suffix decomposition: W_i = sfx_{3-i}(l-2) + T(l-1)+T(l)+T(l+1) + pfx_i(l+2).
// 8 scalar shuffles per array per row (vs 16 for full float4 neighbor exchange).
__device__ __forceinline__ void hwin(const float4 V, int lane,
                                     float& W0, float& W1, float& W2, float& W3) {
    const float pfx1 = V.x;
    const float pfx2 = V.x + V.y;
    const float pfx3 = pfx2 + V.z;
    const float T    = pfx3 + V.w;
    const float sfx1 = V.w;
    const float sfx2 = V.z + V.w;
    const float sfx3 = V.y + sfx2;

    const float s3 = __shfl_sync(0xFFFFFFFFu, sfx3, lane - 2);
    const float s2 = __shfl_sync(0xFFFFFFFFu, sfx2, lane - 2);
    const float s1 = __shfl_sync(0xFFFFFFFFu, sfx1, lane - 2);
    const float p1 = __shfl_sync(0xFFFFFFFFu, pfx1, lane + 2);
    const float p2 = __shfl_sync(0xFFFFFFFFu, pfx2, lane + 2);
    const float p3 = __shfl_sync(0xFFFFFFFFu, pfx3, lane + 2);
    const float Tm = __shfl_sync(0xFFFFFFFFu, T, lane - 1);
    const float Tp = __shfl_sync(0xFFFFFFFFu, T, lane + 1);

    const float base = Tm + T + Tp;
    W0 = base + s3;
    W1 = base + s2 + p1;
    W2 = base + s1 + p2;
    W3 = base + p3;
}

__device__ __forceinline__ void hstep(const float4 VI, const float4 VJ,
                                      bool own, int lane,
                                      float& sII, float& sJJ, float& sIJ) {
    float a0, a1, a2, a3, b0, b1, b2, b3;
    hwin(VI, lane, a0, a1, a2, a3);
    hwin(VJ, lane, b0, b1, b2, b3);
    if (own) {
        sII += a0 * a0 + a1 * a1 + a2 * a2 + a3 * a3;
        sJJ += b0 * b0 + b1 * b1 + b2 * b2 + b3 * b3;
        sIJ += a0 * b0 + a1 * b1 + a2 * b2 + a3 * b3;
    }
}

__global__ void __launch_bounds__(NT)
ncc_fused(const float* __restrict__ I, const float* __restrict__ J,
          float* __restrict__ out) {
    const int tid  = threadIdx.x;
    const int lane = tid & 31;
    const int wrp  = tid >> 5;
    const int bx = blockIdx.x, by = blockIdx.y, bz = blockIdx.z;

    // lane -> float4 column with 2-halo around a 28-wide output segment
    const int c4     = bx * SEG - 2 + lane;          // -2 .. 139
    const bool colok = (c4 >= 0) && (c4 < W4);
    const bool own   = (lane >= 2) && (lane < 2 + SEG) && (c4 < W4);
    const int cx = c4 * 4;

    float wx0 = 0.f, wx1 = 0.f, wx2 = 0.f, wx3 = 0.f;
    if (own) {
        wx0 = (float)(min(cx + 0 + RAD, WW - 1) - max(cx + 0 - RAD, 0) + 1);
        wx1 = (float)(min(cx + 1 + RAD, WW - 1) - max(cx + 1 - RAD, 0) + 1);
        wx2 = (float)(min(cx + 2 + RAD, WW - 1) - max(cx + 2 - RAD, 0) + 1);
        wx3 = (float)(min(cx + 3 + RAD, WW - 1) - max(cx + 3 - RAD, 0) + 1);
    }

    const float4* __restrict__ I4 = (const float4*)I + (size_t)bz * HH * W4;
    const float4* __restrict__ J4 = (const float4*)J + (size_t)bz * HH * W4;

    const int y0 = (by * 8 + wrp) * 8;               // warp's first output row
    const float4 zero = make_float4(0.f, 0.f, 0.f, 0.f);

    float4 VI = zero, VJ = zero;
    float pII = 0.f, pJJ = 0.f, pIJ = 0.f;
    float sII = 0.f, sJJ = 0.f, sIJ = 0.f;

    // ---- init vertical window rows y0-7 .. y0+7 (owned rows at k=7..14) ----
    #pragma unroll
    for (int k = 0; k < WIN; k++) {
        const int gy = y0 - RAD + k;                 // <= 511 always
        float4 vi = zero, vj = zero;
        if (colok && gy >= 0) {
            vi = __ldg(I4 + gy * W4 + c4);
            vj = __ldg(J4 + gy * W4 + c4);
        }
        VI.x += vi.x; VI.y += vi.y; VI.z += vi.z; VI.w += vi.w;
        VJ.x += vj.x; VJ.y += vj.y; VJ.z += vj.z; VJ.w += vj.w;
        if (k >= RAD && own) {                       // owned pixel (gy, cx..cx+3)
            const float wy = (float)(min(gy + RAD, HH - 1) - max(gy - RAD, 0) + 1);
            pII += wy * (wx0 * vi.x * vi.x + wx1 * vi.y * vi.y +
                         wx2 * vi.z * vi.z + wx3 * vi.w * vi.w);
            pJJ += wy * (wx0 * vj.x * vj.x + wx1 * vj.y * vj.y +
                         wx2 * vj.z * vj.z + wx3 * vj.w * vj.w);
            pIJ += wy * (wx0 * vi.x * vj.x + wx1 * vi.y * vj.y +
                         wx2 * vi.z * vj.z + wx3 * vi.w * vj.w);
        }
    }
    hstep(VI, VJ, own, lane, sII, sJJ, sIJ);         // output row y0

    // ---- slides: output rows y0+1 .. y0+7 ----
    #pragma unroll
    for (int j = 0; j < 7; j++) {
        const int gyn = y0 + RAD + 1 + j;
        const int gyo = y0 - RAD + j;
        float4 ni = zero, nj = zero, oi = zero, oj = zero;
        if (colok && gyn < HH) {
            ni = __ldg(I4 + gyn * W4 + c4);
            nj = __ldg(J4 + gyn * W4 + c4);
        }
        if (colok && gyo >= 0) {
            oi = __ldg(I4 + gyo * W4 + c4);           // L1/L2 hit (recent)
            oj = __ldg(J4 + gyo * W4 + c4);
        }
        VI.x += ni.x - oi.x; VI.y += ni.y - oi.y;
        VI.z += ni.z - oi.z; VI.w += ni.w - oi.w;
        VJ.x += nj.x - oj.x; VJ.y += nj.y - oj.y;
        VJ.z += nj.z - oj.z; VJ.w += nj.w - oj.w;
        hstep(VI, VJ, own, lane, sII, sJJ, sIJ);     // output row y0+1+j
    }

    // ---- reductions: float within warp, double across warps/CTAs ----
    float r0 = pII, r1 = pJJ, r2 = pIJ, r3 = sII, r4 = sJJ, r5 = sIJ;
    #pragma unroll
    for (int off = 16; off > 0; off >>= 1) {
        r0 += __shfl_xor_sync(0xFFFFFFFFu, r0, off);
        r1 += __shfl_xor_sync(0xFFFFFFFFu, r1, off);
        r2 += __shfl_xor_sync(0xFFFFFFFFu, r2, off);
        r3 += __shfl_xor_sync(0xFFFFFFFFu, r3, off);
        r4 += __shfl_xor_sync(0xFFFFFFFFu, r4, off);
        r5 += __shfl_xor_sync(0xFFFFFFFFu, r5, off);
    }
    __shared__ double red[NT / 32][6];
    if (lane == 0) {
        red[wrp][0] = (double)r0; red[wrp][1] = (double)r1; red[wrp][2] = (double)r2;
        red[wrp][3] = (double)r3; red[wrp][4] = (double)r4; red[wrp][5] = (double)r5;
    }
    __syncthreads();

    __shared__ int s_last;
    const int bid = bx + GRX * (by + GRY * bz);
    if (tid == 0) {
        double t0 = 0, t1 = 0, t2 = 0, t3 = 0, t4 = 0, t5 = 0;
        #pragma unroll
        for (int w = 0; w < NT / 32; w++) {
            t0 += red[w][0]; t1 += red[w][1]; t2 += red[w][2];
            t3 += red[w][3]; t4 += red[w][4]; t5 += red[w][5];
        }
        g_part[bid][0] = t0; g_part[bid][1] = t1; g_part[bid][2] = t2;
        g_part[bid][3] = t3; g_part[bid][4] = t4; g_part[bid][5] = t5;
        __threadfence();
        unsigned int prev = atomicAdd(&g_count, 1u);
        s_last = (prev == NBLOCKS - 1);
    }
    __syncthreads();

    // ---- last CTA: global reduce + finalize ----
    if (s_last) {
        double c0 = 0, c1 = 0, c2 = 0, c3 = 0, c4d = 0, c5 = 0;
        for (int c = tid; c < NBLOCKS; c += NT) {
            c0 += g_part[c][0]; c1 += g_part[c][1]; c2 += g_part[c][2];
            c3 += g_part[c][3]; c4d += g_part[c][4]; c5 += g_part[c][5];
        }
        __shared__ double red2[NT / 32][6];
        #pragma unroll
        for (int off = 16; off > 0; off >>= 1) {
            c0 += __shfl_xor_sync(0xFFFFFFFFu, c0, off);
            c1 += __shfl_xor_sync(0xFFFFFFFFu, c1, off);
            c2 += __shfl_xor_sync(0xFFFFFFFFu, c2, off);
            c3 += __shfl_xor_sync(0xFFFFFFFFu, c3, off);
            c4d += __shfl_xor_sync(0xFFFFFFFFu, c4d, off);
            c5 += __shfl_xor_sync(0xFFFFFFFFu, c5, off);
        }
        if (lane == 0) {
            red2[wrp][0] = c0; red2[wrp][1] = c1; red2[wrp][2] = c2;
            red2[wrp][3] = c3; red2[wrp][4] = c4d; red2[wrp][5] = c5;
        }
        __syncthreads();
        if (tid == 0) {
            double t0 = 0, t1 = 0, t2 = 0, t3 = 0, t4 = 0, t5 = 0;
            #pragma unroll
            for (int w = 0; w < NT / 32; w++) {
                t0 += red2[w][0]; t1 += red2[w][1]; t2 += red2[w][2];
                t3 += red2[w][3]; t4 += red2[w][4]; t5 += red2[w][5];
            }
            const double inv = 1.0 / 225.0;
            const double cross = t2 - t5 * inv;
            const double iv    = t0 - t3 * inv;
            const double jv    = t1 - t4 * inv;
            out[0] = (float)(-(cross / sqrt(iv * jv)));
            g_count = 0;   // reset for next graph replay
        }
    }
}

extern "C" void kernel_launch(void* const* d_in, const int* in_sizes, int n_in,
                              void* d_out, int out_size) {
    const float* I = (const float*)d_in[0];
    const float* J = (const float*)d_in[1];
    float* out = (float*)d_out;

    dim3 grid(GRX, GRY, BATCH);   // (5, 8, 16) = 640 CTAs
    ncc_fused<<<grid, NT>>>(I, J, out);
}